// round 8
// baseline (speedup 1.0000x reference)
#include <cuda_runtime.h>
#include <cuda_fp16.h>
#include <math.h>

#define NPIX 120
#define NANG 120
#define NK   61
#define NTHR 1024

#define PSTRW 128                    // texel row stride in words (bank = swizzled col & 31)
#define PROWS 128                    // texel rows, padded coords [21,148]
#define PIMG_WORDS (PROWS * PSTRW)   // 16384 (65536 B)
#define SSTR  121                    // fp32 sinogram stride [s][a], odd

#define PIMG_B  0
#define SSINO_B 65536
#define SANG_B  (SSINO_B + 120*121*4)   // 123616
#define STW_B   (SANG_B + 960)
#define SOUT_B  (STW_B + 960)
#define SRED_B  (SOUT_B + 256)
#define SMEM_BYTES (SRED_B + 256)       // ~126 KB

typedef unsigned long long u64;

__device__ __forceinline__ u64 pk2(float lo, float hi) {
    u64 d; asm("mov.b64 %0,{%1,%2};" : "=l"(d) : "f"(lo), "f"(hi)); return d;
}
__device__ __forceinline__ u64 fma2(u64 a, u64 b, u64 c) {
    u64 d; asm("fma.rn.f32x2 %0,%1,%2,%3;" : "=l"(d) : "l"(a), "l"(b), "l"(c)); return d;
}
__device__ __forceinline__ u64 add2(u64 a, u64 b) {
    u64 d; asm("add.rn.f32x2 %0,%1,%2;" : "=l"(d) : "l"(a), "l"(b)); return d;
}

__global__ void __launch_bounds__(NTHR, 1)
ring_kernel(const float* __restrict__ bev, float* __restrict__ out)
{
    extern __shared__ char smraw[];
    unsigned* pimg  = (unsigned*)(smraw + PIMG_B);
    float*    ssino = (float*)(smraw + SSINO_B);
    float2*   sang  = (float2*)(smraw + SANG_B);
    float2*   stw   = (float2*)(smraw + STW_B);
    float*    sout  = (float*)(smraw + SOUT_B);
    float*    sred  = (float*)(smraw + SRED_B);

    const int tid = threadIdx.x;
    const int b   = blockIdx.x;

    unsigned pimg_base;
    {
        unsigned long long tmp;
        asm("cvta.to.shared.u64 %0, %1;" : "=l"(tmp) : "l"((void*)pimg));
        pimg_base = (unsigned)tmp;
    }
    // Phase-2 indices after magic floor are SMALL ints (bias removed exactly):
    // cxs = (xi - 21) ^ (yi & 31);  addr = base + (yi-21)*512 + cxs*4
    const unsigned pb = pimg_base - 21u * 512u;

    // ---- Phase 0: exact trig tables (double precision, once per CTA) ----
    if (tid < NANG) {
        double th = 6.283185307179586476925287 * (double)tid / 119.0;
        double s, c;
        sincos(th, &s, &c);
        sang[tid] = make_float2((float)c, (float)s);
        double ws, wc;
        sincospi((double)tid / 60.0, &ws, &wc);
        stw[tid] = make_float2((float)wc, (float)(-ws));
    }
    if (tid < 64) sout[tid] = 0.0f;
    __syncthreads();

    // ---- Phase 1: fp8-quad texels straight from gmem (windowed + swizzled) ----
    // every (ry, cx) in [0,128)^2 is written -> no zero-init needed
    const float* g = bev + (long)b * (NPIX * NPIX);
    for (int i = tid; i < PROWS * PROWS; i += NTHR) {
        int ry = i >> 7;              // 0..127
        int cx = i & 127;             // 0..127
        int yi = ry + 21;             // padded row coord [21,148]
        int y = yi - 25;              // image coords [-4,123]
        int x = cx - 4;
        float v00 = 0.f, v01 = 0.f, v10 = 0.f, v11 = 0.f;
        bool y0ok = ((unsigned)y < 120u), y1ok = ((unsigned)(y + 1) < 120u);
        bool x0ok = ((unsigned)x < 120u), x1ok = ((unsigned)(x + 1) < 120u);
        if (y0ok && x0ok) v00 = __ldg(g + y * NPIX + x);
        if (y0ok && x1ok) v01 = __ldg(g + y * NPIX + x + 1);
        if (y1ok && x0ok) v10 = __ldg(g + (y + 1) * NPIX + x);
        if (y1ok && x1ok) v11 = __ldg(g + (y + 1) * NPIX + x + 1);
        unsigned short lo, hi;
        asm("cvt.rn.satfinite.e4m3x2.f32 %0, %1, %2;" : "=h"(lo) : "f"(v01), "f"(v00));
        asm("cvt.rn.satfinite.e4m3x2.f32 %0, %1, %2;" : "=h"(hi) : "f"(v11), "f"(v10));
        int colp = cx ^ (yi & 31);    // swizzled column in [0,127]
        pimg[(ry << 7) + colp] = (unsigned)lo | ((unsigned)hi << 16);
    }
    __syncthreads();

    // ---- Phase 2: clipped Radon. 1 swizzled LDS.32 per bilinear sample ----
    const u64 C1  = pk2(8388607.5f, 8388607.5f);   // 2^23 - 0.5 (round -> floor)
    const u64 C2n = pk2(-8388608.0f, -8388608.0f); // -2^23
    const u64 M1  = pk2(-1.0f, -1.0f);
    for (int p = tid; p < NANG * NPIX; p += NTHR) {
        int a  = p / NPIX;
        int si = p - a * NPIX;
        float2 cs = sang[a];
        float ct = cs.x, st = cs.y;
        float sv = (float)si - 59.5f;
        float px0 = fmaf(sv, ct, fmaf(59.5f, st, 84.5f));
        float py0 = fmaf(sv, st, fmaf(-59.5f, ct, 84.5f));
        float dx = -st, dy = ct;

        // clip to nonzero-texel region: px,py in (23.5, 145.5)
        float t0 = 0.0f, t1 = 119.0f;
        if (fabsf(dx) > 1e-9f) {
            float inv = __fdividef(1.0f, dx);
            float A = (23.5f - px0) * inv, B = (145.5f - px0) * inv;
            t0 = fmaxf(t0, fminf(A, B));
            t1 = fminf(t1, fmaxf(A, B));
        } else if (px0 < 23.5f || px0 > 145.5f) t1 = -5.0f;
        if (fabsf(dy) > 1e-9f) {
            float inv = __fdividef(1.0f, dy);
            float A = (23.5f - py0) * inv, B = (145.5f - py0) * inv;
            t0 = fmaxf(t0, fminf(A, B));
            t1 = fminf(t1, fmaxf(A, B));
        } else if (py0 < 23.5f || py0 > 145.5f) t1 = -5.0f;
        t0 = fminf(t0, 126.0f);
        t1 = fmaxf(t1, -6.0f);
        int ta = max(0, (int)t0 - 1);
        int tb = min(119, (int)t1 + 2);

        float acc = 0.0f;
        u64 D = pk2(dx, dy);
        u64 P = fma2(pk2((float)ta, (float)ta), D, pk2(px0, py0));
        #pragma unroll 4
        for (int t = ta; t <= tb; t++) {
            u64 PM = add2(P, C1);                   // 2^23 + floor(p)
            u64 XI = add2(PM, C2n);                 // (xi, yi) as small floats, EXACT
            u64 FR = fma2(XI, M1, P);               // (fx, fy) = P - XI, exact
            unsigned ixb, iyb;
            asm("mov.b64 {%0,%1},%2;" : "=r"(ixb), "=r"(iyb) : "l"(XI));  // small-int bits? no:
            // XI holds floats xi, yi (values 21..148). Use cvt via PM low bits instead:
            asm("mov.b64 {%0,%1},%2;" : "=r"(ixb), "=r"(iyb) : "l"(PM));  // 0x4B000000 + idx
            float fx, fy;
            asm("mov.b64 {%0,%1},%2;" : "=f"(fx), "=f"(fy) : "l"(FR));
            P = add2(P, D);
            unsigned xi = ixb & 0x3FFFFFu;          // strip 2^23 bias bits
            unsigned yi = iyb & 0x3FFFFFu;
            unsigned cxs  = (xi - 21u) ^ (yi & 31u);
            unsigned addr = pb + (yi << 9) + (cxs << 2);
            unsigned quad;
            asm("ld.shared.b32 %0,[%1];" : "=r"(quad) : "r"(addr));
            unsigned topu, botu;
            asm("cvt.rn.f16x2.e4m3x2 %0, %1;" : "=r"(topu) : "h"((unsigned short)quad));
            asm("cvt.rn.f16x2.e4m3x2 %0, %1;" : "=r"(botu) : "h"((unsigned short)(quad >> 16)));
            __half2 top = *(__half2*)&topu;          // (v00, v01)
            __half2 bot = *(__half2*)&botu;          // (v10, v11)
            unsigned fxyu;
            asm("cvt.rn.f16x2.f32 %0, %1, %2;" : "=r"(fxyu) : "f"(fy), "f"(fx)); // hi=fy lo=fx
            __half2 fxy = *(__half2*)&fxyu;
            __half2 dv  = __hsub2(bot, top);
            __half2 fy2 = __half2half2(__high2half(fxy));
            __half2 m   = __hfma2(dv, fy2, top);     // y-lerp
            __half dm   = __hsub(__high2half(m), __low2half(m));
            __half rr   = __hfma(dm, __low2half(fxy), __low2half(m)); // x-lerp
            acc += __half2float(rr);
        }
        ssino[si * SSTR + a] = acc;   // transposed fp32 store, stride 121 (conflict-free)
    }
    __syncthreads();

    // ---- Phase 3a: fold about n=60 (fp32) ----
    for (int it = tid; it < 59 * NANG; it += NTHR) {
        int n = 1 + it / NANG;
        int a = it - (n - 1) * NANG;
        float xa = ssino[n * SSTR + a];
        float xb = ssino[(NPIX - n) * SSTR + a];
        ssino[n * SSTR + a]          = xa + xb;   // xs
        ssino[(NPIX - n) * SSTR + a] = xa - xb;   // xd
    }
    __syncthreads();

    // ---- Phase 3b: folded real DFT, k = 0..60; lanes share k (twiddle broadcast) ----
    for (int it = tid; it < NK * NANG; it += NTHR) {
        int k = it / NANG;
        int a = it - k * NANG;
        const float* v = ssino + a;
        float x0  = v[0];
        float x60 = v[60 * SSTR];
        float re = (k & 1) ? (x0 - x60) : (x0 + x60);
        float im = 0.0f;
        int m = k;
        #pragma unroll 4
        for (int n = 1; n <= 59; n++) {
            float xs = v[n * SSTR];
            float xd = v[(NPIX - n) * SSTR];
            float2 w = stw[m];
            re = fmaf(xs, w.x, re);
            im = fmaf(xd, w.y, im);
            m += k;
            if (m >= NANG) m -= NANG;
        }
        float mag = sqrtf(fmaf(re, re, im * im) * (1.0f / 120.0f) + 1e-15f);
        atomicAdd(&sout[k], mag);
    }
    __syncthreads();

    // ---- Phase 4: L2 norm over mirrored 120-vector, write ----
    if (tid < NK) {
        float v = sout[tid];
        float w = (tid == 0 || tid == 60) ? 1.0f : 2.0f;
        sred[tid] = w * v * v;
    }
    __syncthreads();
    if (tid == 0) {
        float s = 0.0f;
        for (int i = 0; i < NK; i++) s += sred[i];
        sred[63] = fmaxf(sqrtf(s), 1e-12f);
    }
    __syncthreads();
    float inv = 1.0f / sred[63];
    for (int k = tid; k < NPIX; k += NTHR) {
        int kk = (k <= 60) ? k : (NPIX - k);
        out[(long)b * NPIX + k] = sout[kk] * inv;
    }
}

extern "C" void kernel_launch(void* const* d_in, const int* in_sizes, int n_in,
                              void* d_out, int out_size)
{
    const float* bev = (const float*)d_in[0];
    float* out = (float*)d_out;
    int B = in_sizes[0] / (NPIX * NPIX);   // 1024

    cudaFuncSetAttribute(ring_kernel,
                         cudaFuncAttributeMaxDynamicSharedMemorySize, SMEM_BYTES);
    ring_kernel<<<B, NTHR, SMEM_BYTES>>>(bev, out);
}

// round 9
// speedup vs baseline: 1.1749x; 1.1749x over previous
#include <cuda_runtime.h>
#include <cuda_fp16.h>
#include <math.h>

#define NPIX 120
#define NANG 120
#define NK   61
#define NTHR 768

#define PSTRW 133                    // texel row stride in words (133 mod 32 = 5)
#define PROWS 128                    // rows for padded coords yi in [21,148]
#define PIMG_WORDS (PROWS * PSTRW)   // 17024 (68096 B)

#define PIMG_B  0
#define SANG_B  (PIMG_WORDS * 4)         // 68096
#define STW_B   (SANG_B + 960)
#define SOUT_B  (STW_B + 960)
#define SRED_B  (SOUT_B + 256)
#define SMEM_BYTES (SRED_B + 256)        // ~70.5 KB -> 2 CTAs/SM

// global sinogram scratch, transposed [s][a], per-batch 14400 floats
__device__ static float gsino[1024 * NANG * NPIX];

typedef unsigned long long u64;

__device__ __forceinline__ u64 pk2(float lo, float hi) {
    u64 d; asm("mov.b64 %0,{%1,%2};" : "=l"(d) : "f"(lo), "f"(hi)); return d;
}
__device__ __forceinline__ u64 fma2(u64 a, u64 b, u64 c) {
    u64 d; asm("fma.rn.f32x2 %0,%1,%2,%3;" : "=l"(d) : "l"(a), "l"(b), "l"(c)); return d;
}
__device__ __forceinline__ u64 add2(u64 a, u64 b) {
    u64 d; asm("add.rn.f32x2 %0,%1,%2;" : "=l"(d) : "l"(a), "l"(b)); return d;
}

__global__ void __launch_bounds__(NTHR, 2)
ring_kernel(const float* __restrict__ bev, float* __restrict__ out)
{
    extern __shared__ char smraw[];
    unsigned* pimg  = (unsigned*)(smraw + PIMG_B);
    float2*   sang  = (float2*)(smraw + SANG_B);
    float2*   stw   = (float2*)(smraw + STW_B);
    float*    sout  = (float*)(smraw + SOUT_B);
    float*    sred  = (float*)(smraw + SRED_B);

    const int tid = threadIdx.x;
    const int b   = blockIdx.x;
    float* gs = gsino + b * (NANG * NPIX);

    unsigned pimg_base;
    {
        unsigned long long tmp;
        asm("cvta.to.shared.u64 %0, %1;" : "=l"(tmp) : "l"((void*)pimg));
        pimg_base = (unsigned)tmp;
    }
    const unsigned BIASI = 0x4B000000u;   // bit pattern of 2^23
    // tmp = iyb*133 + ixb = BIASI*134 + yi*133 + xi ; addr = pb + tmp*4
    // pb folds base - 4*(BIASI*134 + 21*133 + 21)   (mod 2^32)
    const unsigned pb = pimg_base - (BIASI * 134u + 21u * 133u + 21u) * 4u;

    // ---- Phase 0: exact trig tables (double precision, once per CTA) ----
    if (tid < NANG) {
        double th = 6.283185307179586476925287 * (double)tid / 119.0;
        double s, c;
        sincos(th, &s, &c);
        sang[tid] = make_float2((float)c, (float)s);
        double ws, wc;
        sincospi((double)tid / 60.0, &ws, &wc);
        stw[tid] = make_float2((float)wc, (float)(-ws));
    }
    if (tid < 64) sout[tid] = 0.0f;

    // ---- Phase 1: fp8-quad texels straight from gmem (windowed) ----
    const float* g = bev + (long)b * (NPIX * NPIX);
    for (int i = tid; i < PROWS * PROWS; i += NTHR) {
        int ry = i >> 7;              // 0..127
        int cx = i & 127;             // 0..127
        int y = ry - 4;               // image coords [-4,123] (yi = ry+21, -25)
        int x = cx - 4;
        float v00 = 0.f, v01 = 0.f, v10 = 0.f, v11 = 0.f;
        bool y0ok = ((unsigned)y < 120u), y1ok = ((unsigned)(y + 1) < 120u);
        bool x0ok = ((unsigned)x < 120u), x1ok = ((unsigned)(x + 1) < 120u);
        if (y0ok && x0ok) v00 = __ldg(g + y * NPIX + x);
        if (y0ok && x1ok) v01 = __ldg(g + y * NPIX + x + 1);
        if (y1ok && x0ok) v10 = __ldg(g + (y + 1) * NPIX + x);
        if (y1ok && x1ok) v11 = __ldg(g + (y + 1) * NPIX + x + 1);
        unsigned short lo, hi;
        asm("cvt.rn.satfinite.e4m3x2.f32 %0, %1, %2;" : "=h"(lo) : "f"(v01), "f"(v00));
        asm("cvt.rn.satfinite.e4m3x2.f32 %0, %1, %2;" : "=h"(hi) : "f"(v11), "f"(v10));
        pimg[ry * PSTRW + cx] = (unsigned)lo | ((unsigned)hi << 16);
    }
    __syncthreads();

    // ---- Phase 2: clipped Radon. 1 LDS.32 per bilinear sample ----
    const u64 C1  = pk2(8388607.5f, 8388607.5f);   // 2^23 - 0.5 (round -> floor)
    const u64 C2n = pk2(-8388608.0f, -8388608.0f); // -2^23
    const u64 M1  = pk2(-1.0f, -1.0f);
    for (int p = tid; p < NANG * NPIX; p += NTHR) {
        int a  = p / NPIX;
        int si = p - a * NPIX;
        float2 cs = sang[a];
        float ct = cs.x, st = cs.y;
        float sv = (float)si - 59.5f;
        float px0 = fmaf(sv, ct, fmaf(59.5f, st, 84.5f));
        float py0 = fmaf(sv, st, fmaf(-59.5f, ct, 84.5f));
        float dx = -st, dy = ct;

        // clip to nonzero-texel region: px,py in (23.5, 145.5)
        float t0 = 0.0f, t1 = 119.0f;
        if (fabsf(dx) > 1e-9f) {
            float inv = __fdividef(1.0f, dx);
            float A = (23.5f - px0) * inv, B = (145.5f - px0) * inv;
            t0 = fmaxf(t0, fminf(A, B));
            t1 = fminf(t1, fmaxf(A, B));
        } else if (px0 < 23.5f || px0 > 145.5f) t1 = -5.0f;
        if (fabsf(dy) > 1e-9f) {
            float inv = __fdividef(1.0f, dy);
            float A = (23.5f - py0) * inv, B = (145.5f - py0) * inv;
            t0 = fmaxf(t0, fminf(A, B));
            t1 = fminf(t1, fmaxf(A, B));
        } else if (py0 < 23.5f || py0 > 145.5f) t1 = -5.0f;
        t0 = fminf(t0, 126.0f);
        t1 = fmaxf(t1, -6.0f);
        int ta = max(0, (int)t0 - 1);
        int tb = min(119, (int)t1 + 2);

        float acc = 0.0f;
        u64 D = pk2(dx, dy);
        u64 P = fma2(pk2((float)ta, (float)ta), D, pk2(px0, py0));
        #pragma unroll 4
        for (int t = ta; t <= tb; t++) {
            u64 PM = add2(P, C1);                   // 2^23 + floor(p), bits = BIASI + idx
            u64 XI = add2(PM, C2n);                 // (xi, yi) small floats, exact
            u64 FR = fma2(XI, M1, P);               // (fx, fy) = P - XI, exact
            unsigned ixb, iyb;
            asm("mov.b64 {%0,%1},%2;" : "=r"(ixb), "=r"(iyb) : "l"(PM));
            float fx, fy;
            asm("mov.b64 {%0,%1},%2;" : "=f"(fx), "=f"(fy) : "l"(FR));
            P = add2(P, D);
            unsigned idx  = iyb * 133u + ixb;       // bias folded into pb
            unsigned addr = pb + (idx << 2);
            unsigned quad;
            asm("ld.shared.b32 %0,[%1];" : "=r"(quad) : "r"(addr));
            unsigned topu, botu;
            asm("cvt.rn.f16x2.e4m3x2 %0, %1;" : "=r"(topu) : "h"((unsigned short)quad));
            asm("cvt.rn.f16x2.e4m3x2 %0, %1;" : "=r"(botu) : "h"((unsigned short)(quad >> 16)));
            __half2 top = *(__half2*)&topu;          // (v00, v01)
            __half2 bot = *(__half2*)&botu;          // (v10, v11)
            unsigned fxyu;
            asm("cvt.rn.f16x2.f32 %0, %1, %2;" : "=r"(fxyu) : "f"(fy), "f"(fx)); // hi=fy lo=fx
            __half2 fxy = *(__half2*)&fxyu;
            __half2 dv  = __hsub2(bot, top);
            __half2 fy2 = __half2half2(__high2half(fxy));
            __half2 m   = __hfma2(dv, fy2, top);     // y-lerp
            __half dm   = __hsub(__high2half(m), __low2half(m));
            __half rr   = __hfma(dm, __low2half(fxy), __low2half(m)); // x-lerp
            acc += __half2float(rr);
        }
        gs[si * NPIX + a] = acc;    // transposed scatter to gmem scratch
    }
    __syncthreads();

    // ---- Phase 3: folded real DFT straight from gmem (L1-resident after 1st touch) ----
    for (int it = tid; it < NK * NANG; it += NTHR) {
        int k = it / NANG;
        int a = it - k * NANG;
        const float* v = gs + a;
        float x0  = v[0];
        float x60 = v[60 * NPIX];
        float re = (k & 1) ? (x0 - x60) : (x0 + x60);
        float im = 0.0f;
        int m = k;
        #pragma unroll 4
        for (int n = 1; n <= 59; n++) {
            float xa = v[n * NPIX];
            float xb = v[(NPIX - n) * NPIX];
            float2 w = stw[m];
            re = fmaf(xa + xb, w.x, re);
            im = fmaf(xa - xb, w.y, im);
            m += k;
            if (m >= NANG) m -= NANG;
        }
        float mag = sqrtf(fmaf(re, re, im * im) * (1.0f / 120.0f) + 1e-15f);
        atomicAdd(&sout[k], mag);
    }
    __syncthreads();

    // ---- Phase 4: L2 norm over mirrored 120-vector, write ----
    if (tid < NK) {
        float v = sout[tid];
        float w = (tid == 0 || tid == 60) ? 1.0f : 2.0f;
        sred[tid] = w * v * v;
    }
    __syncthreads();
    if (tid == 0) {
        float s = 0.0f;
        for (int i = 0; i < NK; i++) s += sred[i];
        sred[63] = fmaxf(sqrtf(s), 1e-12f);
    }
    __syncthreads();
    float inv = 1.0f / sred[63];
    for (int k = tid; k < NPIX; k += NTHR) {
        int kk = (k <= 60) ? k : (NPIX - k);
        out[(long)b * NPIX + k] = sout[kk] * inv;
    }
}

extern "C" void kernel_launch(void* const* d_in, const int* in_sizes, int n_in,
                              void* d_out, int out_size)
{
    const float* bev = (const float*)d_in[0];
    float* out = (float*)d_out;
    int B = in_sizes[0] / (NPIX * NPIX);   // 1024

    cudaFuncSetAttribute(ring_kernel,
                         cudaFuncAttributeMaxDynamicSharedMemorySize, SMEM_BYTES);
    ring_kernel<<<B, NTHR, SMEM_BYTES>>>(bev, out);
}